// round 17
// baseline (speedup 1.0000x reference)
#include <cuda_runtime.h>
#include <cuda_fp16.h>
#include <cstdint>
#include <cstddef>

// Problem constants
#define DIAGNUM 50000
#define MEDNUM  20000
#define PRONUM  40000
#define FEATDIM 128
#define N1 (DIAGNUM + MEDNUM)   // 70000
#define N2 (PRONUM + MEDNUM)    // 60000
#define NNZ1 1120000
#define NNZ2 960000
#define CAP 64                  // Poisson(16): P(deg>64) ~ 1e-21 (clamped anyway)

#define NCNT (2 * N1 + 2 * N2)  // 260000 counters

__device__ int  g_cnt[NCNT];
// Bucket entry: (col, v packed as half2 (v,v)). Slots never written are the
// static-zero init (col 0, v=0) — always safe & deterministic to over-read.
__device__ int2 g_bkt1[(size_t)2 * N1 * CAP];      // graph1: lists 0,1
__device__ int2 g_bkt2[(size_t)2 * N2 * CAP];      // graph2: lists 0,1

// fp16 concatenated embedding tables
__device__ __half g_e1[(size_t)N1 * FEATDIM];      // [dEmbed | mEmbed] 17.9 MB
__device__ __half g_e2[(size_t)N2 * FEATDIM];      // [pEmbed | mEmbed] 15.4 MB

// ---------------------------------------------------------------------------
// Zero counters
// ---------------------------------------------------------------------------
__global__ void zero_cnt_kernel() {
    int4* p = reinterpret_cast<int4*>(g_cnt);
    int n4 = NCNT / 4;
    int stride = gridDim.x * blockDim.x;
    int4 z = make_int4(0, 0, 0, 0);
    for (int i = blockIdx.x * blockDim.x + threadIdx.x; i < n4; i += stride)
        p[i] = z;
}

__device__ __forceinline__ int pack_vv(float v) {
    __half hv = __float2half_rn(v);
    __half2 h2v = __half2half2(hv);
    return *reinterpret_cast<int*>(&h2v);
}

// ---------------------------------------------------------------------------
// Fused bucket + convert (co-resident => overlapped).
// ---------------------------------------------------------------------------
#define BUCKET_THREADS 256
#define BUCKET_BLOCKS ((NNZ1 + NNZ2 + BUCKET_THREADS - 1) / BUCKET_THREADS)   // 8125
#define CONV_TOTAL ((N1 + N2) * FEATDIM / 4)                                  // 4,160,000
#define CONV_BLOCKS ((CONV_TOTAL + BUCKET_THREADS - 1) / BUCKET_THREADS)      // 16250

__global__ void prep_kernel(const int* __restrict__ r1, const int* __restrict__ c1,
                            const float* __restrict__ v1,
                            const int* __restrict__ r2, const int* __restrict__ c2,
                            const float* __restrict__ v2,
                            int2* __restrict__ bkt1, int2* __restrict__ bkt2,
                            const float4* __restrict__ dE,
                            const float4* __restrict__ mE,
                            const float4* __restrict__ pE) {
    if (blockIdx.x < BUCKET_BLOCKS) {
        // ------- bucket scatter: two edges per thread; v stored as (v,v) half2
        int tid = blockIdx.x * blockDim.x + threadIdx.x;
        if (tid < NNZ1) {                           // graph1 pair at e = 2*tid
            int e = 2 * tid;
            int list = (e >= NNZ1) ? 1 : 0;
            int2   r = __ldg(reinterpret_cast<const int2*>(r1) + tid);
            int2   c = __ldg(reinterpret_cast<const int2*>(c1) + tid);
            float2 v = __ldg(reinterpret_cast<const float2*>(v1) + tid);
            int base0 = list * N1 + r.x;
            int base1 = list * N1 + r.y;
            int s0 = atomicAdd(&g_cnt[base0], 1);
            int s1 = atomicAdd(&g_cnt[base1], 1);
            if (s0 < CAP) bkt1[(size_t)base0 * CAP + s0] = make_int2(c.x, pack_vv(v.x));
            if (s1 < CAP) bkt1[(size_t)base1 * CAP + s1] = make_int2(c.y, pack_vv(v.y));
        } else {                                    // graph2 pair
            int p = tid - NNZ1;
            if (p >= NNZ2) return;
            int e = 2 * p;
            int list = (e >= NNZ2) ? 1 : 0;
            int2   r = __ldg(reinterpret_cast<const int2*>(r2) + p);
            int2   c = __ldg(reinterpret_cast<const int2*>(c2) + p);
            float2 v = __ldg(reinterpret_cast<const float2*>(v2) + p);
            int base0 = list * N2 + r.x;
            int base1 = list * N2 + r.y;
            int s0 = atomicAdd(&g_cnt[2 * N1 + base0], 1);
            int s1 = atomicAdd(&g_cnt[2 * N1 + base1], 1);
            if (s0 < CAP) bkt2[(size_t)base0 * CAP + s0] = make_int2(c.x, pack_vv(v.x));
            if (s1 < CAP) bkt2[(size_t)base1 * CAP + s1] = make_int2(c.y, pack_vv(v.y));
        }
    } else {
        // ------- fp32 -> fp16 table conversion -------
        const int q1 = N1 * FEATDIM / 4;
        const int q2 = N2 * FEATDIM / 4;
        const int qd = DIAGNUM * FEATDIM / 4;
        const int qp = PRONUM * FEATDIM / 4;
        int i = (blockIdx.x - BUCKET_BLOCKS) * blockDim.x + threadIdx.x;
        if (i < q1) {
            float4 x = (i < qd) ? __ldg(dE + i) : __ldg(mE + (i - qd));
            __half2 lo = __floats2half2_rn(x.x, x.y);
            __half2 hi = __floats2half2_rn(x.z, x.w);
            uint2 packed;
            packed.x = *reinterpret_cast<unsigned*>(&lo);
            packed.y = *reinterpret_cast<unsigned*>(&hi);
            reinterpret_cast<uint2*>(g_e1)[i] = packed;
        } else {
            int j = i - q1;
            if (j >= q2) return;
            float4 x = (j < qp) ? __ldg(pE + j) : __ldg(mE + (j - qp));
            __half2 lo = __floats2half2_rn(x.x, x.y);
            __half2 hi = __floats2half2_rn(x.z, x.w);
            uint2 packed;
            packed.x = *reinterpret_cast<unsigned*>(&lo);
            packed.y = *reinterpret_cast<unsigned*>(&hi);
            reinterpret_cast<uint2*>(g_e2)[j] = packed;
        }
    }
}

// ---------------------------------------------------------------------------
// Core: half-warp per list; 4-edge batches accumulated with HFMA2 into half2,
// flushed to fp32 each batch. READ-ONLY (R15 lesson). Unconditional clamped
// loads only (R14 lesson). Edge loads vectorized 2x int4 (k+3 <= 63 always).
// ---------------------------------------------------------------------------
__device__ __forceinline__ void pair_core(const int2* __restrict__ bktArr,
                                          int b0, int b1, int cntBase,
                                          const uint4* __restrict__ tbl,
                                          int half, int hlane, float acc[8]) {
    int n0 = min(g_cnt[cntBase + b0], CAP);
    int n1 = min(g_cnt[cntBase + b1], CAP);
    int nmax = max(n0, n1);
    int nmy  = half ? n1 : n0;
    const int2* myBkt = bktArr + (size_t)(half ? b1 : b0) * CAP;

    #pragma unroll
    for (int i = 0; i < 8; i++) acc[i] = 0.f;
    const __half2 hz = __float2half2_rn(0.f);

    for (int k = 0; k < nmax; k += 4) {
        // 4 edges via two int4 loads (slots k..k+3 always within CAP)
        int4 p = __ldg(reinterpret_cast<const int4*>(myBkt + k));
        int4 q = __ldg(reinterpret_cast<const int4*>(myBkt + k + 2));
        int  cols[4] = {p.x, p.z, q.x, q.z};
        int  vraw[4] = {p.y, p.w, q.y, q.w};

        uint4 x[4];
        __half2 hv[4];
        #pragma unroll
        for (int j = 0; j < 4; j++) {
            int vv = (k + j < nmy) ? vraw[j] : 0;   // padded => (0,0) half2
            hv[j] = *reinterpret_cast<__half2*>(&vv);
            x[j] = __ldg(tbl + (size_t)cols[j] * 16 + hlane);
        }

        __half2 h0 = hz, h1 = hz, h2 = hz, h3 = hz;
        #pragma unroll
        for (int j = 0; j < 4; j++) {
            h0 = __hfma2(hv[j], *reinterpret_cast<__half2*>(&x[j].x), h0);
            h1 = __hfma2(hv[j], *reinterpret_cast<__half2*>(&x[j].y), h1);
            h2 = __hfma2(hv[j], *reinterpret_cast<__half2*>(&x[j].z), h2);
            h3 = __hfma2(hv[j], *reinterpret_cast<__half2*>(&x[j].w), h3);
        }
        // flush batch to fp32
        float2 f0 = __half22float2(h0);
        float2 f1 = __half22float2(h1);
        float2 f2 = __half22float2(h2);
        float2 f3 = __half22float2(h3);
        acc[0] += f0.x; acc[1] += f0.y;
        acc[2] += f1.x; acc[3] += f1.y;
        acc[4] += f2.x; acc[5] += f2.y;
        acc[6] += f3.x; acc[7] += f3.y;
    }

    #pragma unroll
    for (int i = 0; i < 8; i++) acc[i] = fmaxf(acc[i], 0.f);
    #pragma unroll
    for (int i = 0; i < 8; i++) acc[i] += __shfl_xor_sync(0xffffffffu, acc[i], 16);
}

// ---------------------------------------------------------------------------
// Gather: one warp per TASK; m-tasks (2x work) first (LPT). Plain stores only.
// ---------------------------------------------------------------------------
#define NTASKS 110000

__global__ void __launch_bounds__(256) gather_kernel(const float* __restrict__ inter,
                                                     float4* __restrict__ out) {
    int task = (blockIdx.x * blockDim.x + threadIdx.x) >> 5;
    int lane = threadIdx.x & 31;
    if (task >= NTASKS) return;
    int half  = lane >> 4;
    int hlane = lane & 15;

    float res8[8];
    int outRow;

    if (task < MEDNUM) {                        // m-row: both graphs, blend
        int m = task;
        float a1[8], a2[8];
        pair_core(g_bkt1, DIAGNUM + m, N1 + DIAGNUM + m, 0,
                  reinterpret_cast<const uint4*>(g_e1), half, hlane, a1);
        pair_core(g_bkt2, PRONUM + m, N2 + PRONUM + m, 2 * N1,
                  reinterpret_cast<const uint4*>(g_e2), half, hlane, a2);
        float t = __ldg(inter);
        float u = 1.f - t;
        #pragma unroll
        for (int i = 0; i < 8; i++) res8[i] = t * a1[i] + u * a2[i];
        outRow = m;
    } else if (task < MEDNUM + DIAGNUM) {       // d-row, graph1
        int r = task - MEDNUM;
        pair_core(g_bkt1, r, N1 + r, 0,
                  reinterpret_cast<const uint4*>(g_e1), half, hlane, res8);
        outRow = MEDNUM + r;
    } else {                                    // p-row, graph2
        int r = task - MEDNUM - DIAGNUM;
        pair_core(g_bkt2, r, N2 + r, 2 * N1,
                  reinterpret_cast<const uint4*>(g_e2), half, hlane, res8);
        outRow = MEDNUM + DIAGNUM + r;
    }

    float4 res = half ? make_float4(res8[4], res8[5], res8[6], res8[7])
                      : make_float4(res8[0], res8[1], res8[2], res8[3]);
    res.x *= 2.f; res.y *= 2.f; res.z *= 2.f; res.w *= 2.f;
    out[(size_t)outRow * 32 + 2 * hlane + half] = res;
}

// ---------------------------------------------------------------------------
extern "C" void kernel_launch(void* const* d_in, const int* in_sizes, int n_in,
                              void* d_out, int out_size) {
    const int*   a1r = (const int*)d_in[0];
    const int*   a1c = (const int*)d_in[1];
    const float* a1v = (const float*)d_in[2];
    const int*   a2r = (const int*)d_in[3];
    const int*   a2c = (const int*)d_in[4];
    const float* a2v = (const float*)d_in[5];
    const float4* dE = (const float4*)d_in[6];
    const float4* mE = (const float4*)d_in[7];
    const float4* pE = (const float4*)d_in[8];
    const float* inter = (const float*)d_in[9];
    float4* out = (float4*)d_out;

    int2* bkt1;  cudaGetSymbolAddress((void**)&bkt1, g_bkt1);
    int2* bkt2;  cudaGetSymbolAddress((void**)&bkt2, g_bkt2);

    // 1. Zero counters (tiny)
    zero_cnt_kernel<<<128, 256>>>();

    // 2. Fused bucket (first, longer) + fp16 conversion (fills remaining SMs)
    prep_kernel<<<BUCKET_BLOCKS + CONV_BLOCKS, BUCKET_THREADS>>>(
        a1r, a1c, a1v, a2r, a2c, a2v, bkt1, bkt2, dE, mE, pE);

    // 3. Gather: m-tasks first (2x work), then d/p; all plain stores
    {
        int threads = 256;
        int blocks = (NTASKS * 32 + threads - 1) / threads;
        gather_kernel<<<blocks, threads>>>(inter, out);
    }
}